// round 3
// baseline (speedup 1.0000x reference)
#include <cuda_runtime.h>
#include <math.h>

#define N_NODES 100000
#define N_EDGES 3200000
#define F0 512
#define F1 256
#define F2 64

// ---------------- scratch (__device__ globals; allocation-free) ----------------
__device__ float g_support1[(size_t)N_NODES * F1];   // x @ w1
__device__ float g_h[(size_t)N_NODES * F1];          // relu(spmm1 + b1)
__device__ float g_support2[(size_t)N_NODES * F2];   // h @ w2
__device__ int   g_deg[N_NODES];
__device__ int   g_rowptr[N_NODES + 1];
__device__ int   g_cursor[N_NODES];
__device__ int   g_csr_src[N_EDGES];
__device__ float g_csr_w[N_EDGES];

// ---------------- CSR build ----------------
__global__ void zero_deg_kernel() {
    int i = blockIdx.x * blockDim.x + threadIdx.x;
    if (i < N_NODES) g_deg[i] = 0;
}

__global__ void hist_kernel(const int* __restrict__ edge_dst) {
    int e = blockIdx.x * blockDim.x + threadIdx.x;
    if (e < N_EDGES) atomicAdd(&g_deg[edge_dst[e]], 1);
}

// single-block exact exclusive scan of g_deg -> g_rowptr
__global__ void scan_kernel() {
    __shared__ int ssum[1024];
    const int t = threadIdx.x;
    const int CHUNK = (N_NODES + 1023) / 1024;  // 98
    int start = t * CHUNK;
    int end = min(start + CHUNK, N_NODES);
    int s = 0;
    for (int i = start; i < end; i++) s += g_deg[i];
    ssum[t] = s;
    __syncthreads();
    // Hillis-Steele inclusive scan over 1024
    for (int off = 1; off < 1024; off <<= 1) {
        int v = 0;
        if (t >= off) v = ssum[t - off];
        __syncthreads();
        if (t >= off) ssum[t] += v;
        __syncthreads();
    }
    int run = (t == 0) ? 0 : ssum[t - 1];
    for (int i = start; i < end; i++) { g_rowptr[i] = run; run += g_deg[i]; }
    if (t == 1023) g_rowptr[N_NODES] = run;   // == N_EDGES
}

__global__ void copy_cursor_kernel() {
    int i = blockIdx.x * blockDim.x + threadIdx.x;
    if (i < N_NODES) g_cursor[i] = g_rowptr[i];
}

__global__ void fill_kernel(const int* __restrict__ edge_src,
                            const int* __restrict__ edge_dst,
                            const float* __restrict__ edge_w) {
    int e = blockIdx.x * blockDim.x + threadIdx.x;
    if (e < N_EDGES) {
        int d = edge_dst[e];
        int p = atomicAdd(&g_cursor[d], 1);
        g_csr_src[p] = edge_src[e];
        g_csr_w[p]   = edge_w[e];
    }
}

// ---------------- tiled fp32 GEMM: C[M,N] = A[M,K] @ B[K,N] ----------------
// BM=128, BN=64, BK=16, TM=8, TN=4, blockDim (16,16)
__global__ __launch_bounds__(256) void gemm_kernel(
    const float* __restrict__ A, const float* __restrict__ B, float* __restrict__ C,
    int M, int N, int K)
{
    const int BM = 128, BN = 64, BK = 16, TM = 8, TN = 4;
    __shared__ float Ast[BK][BM + 4];   // transposed A tile, padded
    __shared__ float Bs[BK][BN];

    const int tx = threadIdx.x, ty = threadIdx.y;
    const int tid = ty * 16 + tx;
    const int row0 = blockIdx.y * BM;
    const int col0 = blockIdx.x * BN;

    float acc[TM][TN];
#pragma unroll
    for (int i = 0; i < TM; i++)
#pragma unroll
        for (int j = 0; j < TN; j++) acc[i][j] = 0.f;

    for (int k0 = 0; k0 < K; k0 += BK) {
        // A tile: 128x16 floats = 512 float4, 2 per thread
#pragma unroll
        for (int it = 0; it < 2; it++) {
            int idx4 = tid + it * 256;
            int r = idx4 >> 2;
            int c4 = idx4 & 3;
            float4 v = make_float4(0.f, 0.f, 0.f, 0.f);
            int gr = row0 + r;
            if (gr < M) v = *(const float4*)&A[(size_t)gr * K + k0 + c4 * 4];
            Ast[c4 * 4 + 0][r] = v.x;
            Ast[c4 * 4 + 1][r] = v.y;
            Ast[c4 * 4 + 2][r] = v.z;
            Ast[c4 * 4 + 3][r] = v.w;
        }
        // B tile: 16x64 floats = 256 float4, 1 per thread
        {
            int r = tid >> 4;
            int c4 = tid & 15;
            *(float4*)&Bs[r][c4 * 4] = *(const float4*)&B[(size_t)(k0 + r) * N + col0 + c4 * 4];
        }
        __syncthreads();

#pragma unroll
        for (int kk = 0; kk < BK; kk++) {
            float a[TM], b[TN];
            float4 a0 = *(const float4*)&Ast[kk][ty * TM];
            float4 a1 = *(const float4*)&Ast[kk][ty * TM + 4];
            a[0]=a0.x; a[1]=a0.y; a[2]=a0.z; a[3]=a0.w;
            a[4]=a1.x; a[5]=a1.y; a[6]=a1.z; a[7]=a1.w;
            float4 b0 = *(const float4*)&Bs[kk][tx * TN];
            b[0]=b0.x; b[1]=b0.y; b[2]=b0.z; b[3]=b0.w;
#pragma unroll
            for (int i = 0; i < TM; i++)
#pragma unroll
                for (int j = 0; j < TN; j++)
                    acc[i][j] = fmaf(a[i], b[j], acc[i][j]);
        }
        __syncthreads();
    }

#pragma unroll
    for (int i = 0; i < TM; i++) {
        int gr = row0 + ty * TM + i;
        if (gr < M) {
            float4 v = make_float4(acc[i][0], acc[i][1], acc[i][2], acc[i][3]);
            *(float4*)&C[(size_t)gr * N + col0 + tx * TN] = v;
        }
    }
}

// ---------------- SpMM layer 1: h = relu(adj @ support1 + b1), F=256 ----------------
// Warp per row. Lane l owns features [4l,4l+4) and [128+4l,128+4l+4).
__global__ __launch_bounds__(256) void spmm1_relu_kernel(const float* __restrict__ b1) {
    const int row = blockIdx.x * 8 + (threadIdx.x >> 5);
    const int lane = threadIdx.x & 31;
    if (row >= N_NODES) return;

    const int beg = g_rowptr[row];
    const int end = g_rowptr[row + 1];

    float4 acc0 = make_float4(0.f, 0.f, 0.f, 0.f);
    float4 acc1 = make_float4(0.f, 0.f, 0.f, 0.f);

    for (int base = beg; base < end; base += 32) {
        int j = base + lane;
        int s = 0; float w = 0.f;
        if (j < end) { s = g_csr_src[j]; w = g_csr_w[j]; }
        int n = min(32, end - base);
        for (int t = 0; t < n; t++) {
            int   ss = __shfl_sync(0xffffffffu, s, t);
            float ww = __shfl_sync(0xffffffffu, w, t);
            const float4* p = (const float4*)&g_support1[(size_t)ss * F1];
            float4 v0 = p[lane];
            float4 v1 = p[lane + 32];
            acc0.x = fmaf(ww, v0.x, acc0.x);
            acc0.y = fmaf(ww, v0.y, acc0.y);
            acc0.z = fmaf(ww, v0.z, acc0.z);
            acc0.w = fmaf(ww, v0.w, acc0.w);
            acc1.x = fmaf(ww, v1.x, acc1.x);
            acc1.y = fmaf(ww, v1.y, acc1.y);
            acc1.z = fmaf(ww, v1.z, acc1.z);
            acc1.w = fmaf(ww, v1.w, acc1.w);
        }
    }

    float4 bb0 = ((const float4*)b1)[lane];
    float4 bb1 = ((const float4*)b1)[lane + 32];
    float4 o0, o1;
    o0.x = fmaxf(acc0.x + bb0.x, 0.f);
    o0.y = fmaxf(acc0.y + bb0.y, 0.f);
    o0.z = fmaxf(acc0.z + bb0.z, 0.f);
    o0.w = fmaxf(acc0.w + bb0.w, 0.f);
    o1.x = fmaxf(acc1.x + bb1.x, 0.f);
    o1.y = fmaxf(acc1.y + bb1.y, 0.f);
    o1.z = fmaxf(acc1.z + bb1.z, 0.f);
    o1.w = fmaxf(acc1.w + bb1.w, 0.f);

    float4* pout = (float4*)&g_h[(size_t)row * F1];
    pout[lane] = o0;
    pout[lane + 32] = o1;
}

// ---------------- SpMM layer 2 + bias + log_softmax, F=64 ----------------
// Warp per row. Lane l owns features 2l, 2l+1. Warp-shuffle softmax.
__global__ __launch_bounds__(256) void spmm2_softmax_kernel(const float* __restrict__ b2,
                                                            float* __restrict__ out) {
    const int row = blockIdx.x * 8 + (threadIdx.x >> 5);
    const int lane = threadIdx.x & 31;
    if (row >= N_NODES) return;

    const int beg = g_rowptr[row];
    const int end = g_rowptr[row + 1];

    float2 acc = make_float2(0.f, 0.f);
    for (int base = beg; base < end; base += 32) {
        int j = base + lane;
        int s = 0; float w = 0.f;
        if (j < end) { s = g_csr_src[j]; w = g_csr_w[j]; }
        int n = min(32, end - base);
        for (int t = 0; t < n; t++) {
            int   ss = __shfl_sync(0xffffffffu, s, t);
            float ww = __shfl_sync(0xffffffffu, w, t);
            float2 v = ((const float2*)&g_support2[(size_t)ss * F2])[lane];
            acc.x = fmaf(ww, v.x, acc.x);
            acc.y = fmaf(ww, v.y, acc.y);
        }
    }

    float2 bb = ((const float2*)b2)[lane];
    acc.x += bb.x;
    acc.y += bb.y;

    // warp-wide max over 64 values
    float m = fmaxf(acc.x, acc.y);
#pragma unroll
    for (int off = 16; off > 0; off >>= 1)
        m = fmaxf(m, __shfl_xor_sync(0xffffffffu, m, off));
    // warp-wide sum of exp
    float s = expf(acc.x - m) + expf(acc.y - m);
#pragma unroll
    for (int off = 16; off > 0; off >>= 1)
        s += __shfl_xor_sync(0xffffffffu, s, off);
    float ls = logf(s);

    float2 o;
    o.x = acc.x - m - ls;
    o.y = acc.y - m - ls;
    ((float2*)&out[(size_t)row * F2])[lane] = o;
}

// ---------------- launch ----------------
extern "C" void kernel_launch(void* const* d_in, const int* in_sizes, int n_in,
                              void* d_out, int out_size) {
    const float* x    = (const float*)d_in[0];
    const float* w1   = (const float*)d_in[1];
    const float* b1   = (const float*)d_in[2];
    const float* w2   = (const float*)d_in[3];
    const float* b2   = (const float*)d_in[4];
    const float* ew   = (const float*)d_in[5];
    const int*   esrc = (const int*)d_in[6];
    const int*   edst = (const int*)d_in[7];
    float* out = (float*)d_out;

    float* support1; cudaGetSymbolAddress((void**)&support1, g_support1);
    float* h;        cudaGetSymbolAddress((void**)&h,        g_h);
    float* support2; cudaGetSymbolAddress((void**)&support2, g_support2);

    // CSR build
    zero_deg_kernel<<<(N_NODES + 255) / 256, 256>>>();
    hist_kernel<<<(N_EDGES + 255) / 256, 256>>>(edst);
    scan_kernel<<<1, 1024>>>();
    copy_cursor_kernel<<<(N_NODES + 255) / 256, 256>>>();
    fill_kernel<<<(N_EDGES + 255) / 256, 256>>>(esrc, edst, ew);

    // GEMM1: support1 = x @ w1   [100000,512]x[512,256]
    {
        dim3 grid(F1 / 64, (N_NODES + 127) / 128);
        dim3 block(16, 16);
        gemm_kernel<<<grid, block>>>(x, w1, support1, N_NODES, F1, F0);
    }

    // SpMM1 + bias + relu (warp per row, 8 rows/block)
    spmm1_relu_kernel<<<(N_NODES + 7) / 8, 256>>>(b1);

    // GEMM2: support2 = h @ w2   [100000,256]x[256,64]
    {
        dim3 grid(F2 / 64, (N_NODES + 127) / 128);
        dim3 block(16, 16);
        gemm_kernel<<<grid, block>>>(h, w2, support2, N_NODES, F2, F1);
    }

    // SpMM2 + bias + log_softmax (warp per row, 8 rows/block)
    spmm2_softmax_kernel<<<(N_NODES + 7) / 8, 256>>>(b2, out);
}